// round 17
// baseline (speedup 1.0000x reference)
#include <cuda_runtime.h>

#define NEMB      512
#define QBLOCKS   256
#define QTHREADS  512
#define CWPB      (NEMB / QBLOCKS)           // 2 codewords per block
#define LUT_SIZE  2048
#define LUT_CHUNK (LUT_SIZE / QTHREADS)      // 4 buckets per thread
#define NGRP      8
#define GSTRIDE   32                         // 128 B between counters

__device__ float        g_sval[NEMB];
__device__ unsigned int g_rdy1[NGRP * GSTRIDE];
__device__ unsigned int g_rdy2;
__device__ volatile unsigned int g_all_ready;
__device__ float        g_lossAcc[NGRP * GSTRIDE];
__device__ unsigned int g_done1[NGRP * GSTRIDE];
__device__ unsigned int g_done2;

// The ONE bucket map used by both LUT build and queries (fp-consistent,
// monotone): bucket(a) < bucket(b) implies a < b.
__device__ __forceinline__ int bucket_of(float v, float vmin, float inv) {
    int b = (int)(__fmul_rn(__fadd_rn(v, -vmin), inv));
    return min(max(b, 0), LUT_SIZE - 1);
}

__global__ void __launch_bounds__(QTHREADS, 2)
vq_fused_kernel(const float* __restrict__ x,
                const float* __restrict__ emb,
                float* __restrict__ out,
                int n, int write_loss) {
    __shared__ float s_emb[NEMB];
    __shared__ float sval[NEMB];
    __shared__ short lut[LUT_SIZE];
    __shared__ int   s_rank[CWPB];
    __shared__ float s_part[QTHREADS / 32];

    const int tid = threadIdx.x;
    const int bid = blockIdx.x;
    const int grp = bid & (NGRP - 1);

    // ---- Prefetch this thread's 2 elements (independent of codebook) ------
    const int c    = bid * QTHREADS + tid;
    const int base = c * 2;
    const bool full = (base + 1 < n);
    float2 v = make_float2(0.f, 0.f);
    if (full) v = *reinterpret_cast<const float2*>(x + base);

    // ---- Phase 1: every block rank-sorts its 2 codewords ------------------
    if (tid < CWPB) s_rank[tid] = 0;
    if (tid < NEMB / 4) {
        const float4 e = __ldg(&reinterpret_cast<const float4*>(emb)[tid]);
        reinterpret_cast<float4*>(s_emb)[tid] = e;
    }
    __syncthreads();

    {
        const int g  = tid >> 8;                         // 0..1 codeword group
        const int cw = bid * CWPB + g;                   // original index
        const int l  = tid & 255;                        // lane in group
        const float cv = s_emb[cw];
        const float2 e = reinterpret_cast<const float2*>(s_emb)[l];
        const int j = l * 2;
        int partial = 0;
        partial += (int)(e.x < cv) + (int)((e.x == cv) && (j + 0 < cw));
        partial += (int)(e.y < cv) + (int)((e.y == cv) && (j + 1 < cw));
        #pragma unroll
        for (int off = 16; off > 0; off >>= 1)
            partial += __shfl_xor_sync(0xFFFFFFFFu, partial, off);
        if ((tid & 31) == 0) atomicAdd(&s_rank[g], partial);
    }
    __syncthreads();

    if (tid < CWPB) {
        const int mycw = bid * CWPB + tid;
        const int r = s_rank[tid];             // exact permutation (keys unique)
        g_sval[r] = s_emb[mycw];
        __threadfence();                       // publish before counting ready
    }
    __syncthreads();

    // ---- Ready barrier: 8-way level-1 chains -> level-2 -> one poll word --
    if (tid == 0) {
        const unsigned r = atomicAdd(&g_rdy1[grp * GSTRIDE], 1u);
        if (r == (QBLOCKS / NGRP) - 1) {
            const unsigned r2 = atomicAdd(&g_rdy2, 1u);
            if (r2 == NGRP - 1)
                g_all_ready = 1u;
        }
        while (g_all_ready == 0u) { }          // single-word read spin
    }
    __syncthreads();

    // ---- Copy sorted codebook (L2 is the coherence point) -----------------
    if (tid < NEMB / 4) {
        const float4 vv = __ldcg(&reinterpret_cast<const float4*>(g_sval)[tid]);
        reinterpret_cast<float4*>(sval)[tid] = vv;
    }
    __syncthreads();

    const float vmin = sval[0];
    const float vmax = sval[NEMB - 1];
    const float rng  = __fadd_rn(vmax, -vmin);
    const float inv  = (rng > 0.0f) ? __fdiv_rn((float)LUT_SIZE, rng) : 0.0f;

    // ---- Build LUT: lut[k] = (min{ j : bucket(sval[j]) >= k }) - 1 --------
    // (clamped to [0, NEMB-2]; query candidates are sval[lut[k]], sval[lut[k]+1])
    {
        const int k0 = tid * LUT_CHUNK;
        int lo = 0, hi = NEMB;
        #pragma unroll
        for (int it = 0; it < 10; it++) {
            const int mid = (lo + hi) >> 1;
            if (hi > lo) {
                if (bucket_of(sval[mid], vmin, inv) < k0) lo = mid + 1;
                else hi = mid;
            }
        }
        int curb = (lo < NEMB) ? bucket_of(sval[lo], vmin, inv) : LUT_SIZE;
        #pragma unroll
        for (int j = 0; j < LUT_CHUNK; j++) {
            const int k = k0 + j;
            while (curb < k) {
                lo++;
                curb = (lo < NEMB) ? bucket_of(sval[lo], vmin, inv) : LUT_SIZE;
            }
            lut[k] = (short)min(max(lo - 1, 0), NEMB - 2);
        }
    }
    __syncthreads();

    // ---- Quantize: LUT start + expected ~0.25-step scan + 2-candidate pick -
    float local = 0.0f;

    if (full) {
        float vv[2] = {v.x, v.y};
        float qq[2];
        #pragma unroll
        for (int e = 0; e < 2; e++) {
            const float xv = vv[e];
            const int k = bucket_of(xv, vmin, inv);
            int j = (int)lut[k];
            float b = sval[j + 1];
            while (b < xv && j < NEMB - 2) { j++; b = sval[j + 1]; }
            const float a = sval[j];
            const float da = __fadd_rn(xv, -a);
            const float db = __fadd_rn(xv, -b);
            const float ea = __fmul_rn(da, da);
            const float eb = __fmul_rn(db, db);
            qq[e] = (ea <= eb) ? a : b;
            local += fminf(ea, eb);
        }
        float2 o;
        o.x = qq[0]; o.y = qq[1];
        *reinterpret_cast<float2*>(out + base) = o;
    } else {
        for (int i = base; i < n && i < base + 2; i++) {
            const float xv = x[i];
            const int k = bucket_of(xv, vmin, inv);
            int j = (int)lut[k];
            float b = sval[j + 1];
            while (b < xv && j < NEMB - 2) { j++; b = sval[j + 1]; }
            const float a = sval[j];
            const float da = __fadd_rn(xv, -a);
            const float db = __fadd_rn(xv, -b);
            const float ea = __fmul_rn(da, da);
            const float eb = __fmul_rn(db, db);
            out[i] = (ea <= eb) ? a : b;
            local += fminf(ea, eb);
        }
    }

    // ---- Loss: warp shuffle -> smem array -> warp-0 reduce ----------------
    #pragma unroll
    for (int off = 16; off > 0; off >>= 1)
        local += __shfl_xor_sync(0xFFFFFFFFu, local, off);
    if ((tid & 31) == 0)
        s_part[tid >> 5] = local;
    __syncthreads();

    if (tid < 32) {
        float t = (tid < QTHREADS / 32) ? s_part[tid] : 0.0f;
        #pragma unroll
        for (int off = 8; off > 0; off >>= 1)
            t += __shfl_xor_sync(0xFFFFFFFFu, t, off);

        // ---- last-done block finalizes + resets (graph replay) ------------
        if (tid == 0) {
            atomicAdd(&g_lossAcc[grp * GSTRIDE], t);
            __threadfence();
            const unsigned d = atomicAdd(&g_done1[grp * GSTRIDE], 1u);
            if (d == (QBLOCKS / NGRP) - 1) {
                const unsigned d2 = atomicAdd(&g_done2, 1u);
                if (d2 == NGRP - 1) {
                    float total = 0.0f;
                    #pragma unroll
                    for (int i = 0; i < NGRP; i++)
                        total += __ldcg(&g_lossAcc[i * GSTRIDE]);
                    if (write_loss)
                        out[n] = 1.25f * total / (float)n;
                    #pragma unroll
                    for (int i = 0; i < NGRP; i++) {
                        g_rdy1[i * GSTRIDE]    = 0u;
                        g_done1[i * GSTRIDE]   = 0u;
                        g_lossAcc[i * GSTRIDE] = 0.0f;
                    }
                    g_rdy2 = 0u;
                    g_done2 = 0u;
                    g_all_ready = 0u;
                }
            }
        }
    }
}

extern "C" void kernel_launch(void* const* d_in, const int* in_sizes, int n_in,
                              void* d_out, int out_size) {
    const float* x   = (const float*)d_in[0];   // pre_quantized, 16*1*128*128
    const float* emb = (const float*)d_in[1];   // emb_weight, 512*1
    float* out = (float*)d_out;

    const int n = in_sizes[0];                  // 262144
    const int write_loss = (out_size > n) ? 1 : 0;

    vq_fused_kernel<<<QBLOCKS, QTHREADS>>>(x, emb, out, n, write_loss);
}